// round 13
// baseline (speedup 1.0000x reference)
#include <cuda_runtime.h>
#include <cuda_fp16.h>
#include <math.h>
#include <stdint.h>

// ============================================================================
// B=2, S=2048, E=1024, H=16, D=64.  M = 4096.
// All matmuls 1-term fp16 on mma.sync (HMMA; tcgen05 not compilable here).
// This round: GEMMs reshaped to BM=64/BN=128, 128 thr, 4 CTAs/SM
// (4 independent barrier domains instead of 2 at the same warp count).
// ============================================================================

#define E_DIM 1024
#define NH    16
#define HD    64
#define S_LEN 2048
#define MAX_M 4096
#define NELEM 4194304
#define WELEM 1048576

__device__ __half g_xh[NELEM];
__device__ __half g_wh[4 * WELEM];
__device__ __half g_qh[NELEM];
__device__ __half g_kh[NELEM];
__device__ __half g_vh[NELEM];
__device__ __half g_ah[NELEM];     // attention output (fp16), outproj A-side

// ---- helpers ----
__device__ __forceinline__ void mma_f16(float c[4],
    uint32_t a0, uint32_t a1, uint32_t a2, uint32_t a3,
    uint32_t b0, uint32_t b1)
{
    asm volatile(
        "mma.sync.aligned.m16n8k16.row.col.f32.f16.f16.f32 "
        "{%0,%1,%2,%3}, {%4,%5,%6,%7}, {%8,%9}, {%0,%1,%2,%3};"
        : "+f"(c[0]), "+f"(c[1]), "+f"(c[2]), "+f"(c[3])
        : "r"(a0), "r"(a1), "r"(a2), "r"(a3), "r"(b0), "r"(b1));
}

__device__ __forceinline__ float ex2f(float x) {
    float y;
    asm("ex2.approx.ftz.f32 %0, %1;" : "=f"(y) : "f"(x));
    return y;
}

__device__ __forceinline__ uint32_t pack2h(float x, float y) {
    __half2 t = __halves2half2(__float2half_rn(x), __float2half_rn(y));
    return *reinterpret_cast<uint32_t*>(&t);
}

__device__ __forceinline__ uint32_t smem_u32(const void* p) {
    return (uint32_t)__cvta_generic_to_shared(p);
}

__device__ __forceinline__ void ldsm4(uint32_t& r0, uint32_t& r1,
                                      uint32_t& r2, uint32_t& r3, uint32_t a) {
    asm volatile("ldmatrix.sync.aligned.m8n8.x4.shared.b16 {%0,%1,%2,%3}, [%4];"
        : "=r"(r0), "=r"(r1), "=r"(r2), "=r"(r3) : "r"(a));
}

__device__ __forceinline__ void ldsm4t(uint32_t& r0, uint32_t& r1,
                                       uint32_t& r2, uint32_t& r3, uint32_t a) {
    asm volatile("ldmatrix.sync.aligned.m8n8.x4.trans.shared.b16 {%0,%1,%2,%3}, [%4];"
        : "=r"(r0), "=r"(r1), "=r"(r2), "=r"(r3) : "r"(a));
}

__device__ __forceinline__ void cp16(uint32_t dst, const void* src) {
    asm volatile("cp.async.cg.shared.global [%0], [%1], 16;"
        :: "r"(dst), "l"(src));
}
#define CP_COMMIT() asm volatile("cp.async.commit_group;")
#define CP_WAIT0()  asm volatile("cp.async.wait_group 0;")

// ============================================================================
// Convert: x and 4 weight matrices -> fp16 (float4-vectorized)
// ============================================================================
__global__ __launch_bounds__(256) void split_kernel(
    const float* __restrict__ x,
    const float* __restrict__ Wq, const float* __restrict__ Wk,
    const float* __restrict__ Wv, const float* __restrict__ Wo)
{
    const int i4 = (blockIdx.x * 256 + threadIdx.x) * 4;
    const float* src;
    __half* dst;
    if (i4 < NELEM) {
        src = x + i4;
        dst = g_xh + i4;
    } else {
        const int j4 = i4 - NELEM;
        const int w  = j4 >> 20;
        const int off = j4 & (WELEM - 1);
        const float* W = (w == 0) ? Wq : (w == 1) ? Wk : (w == 2) ? Wv : Wo;
        src = W + off;
        dst = g_wh + j4;
    }
    const float4 v = *reinterpret_cast<const float4*>(src);
    uint2 p;
    p.x = pack2h(v.x, v.y);
    p.y = pack2h(v.z, v.w);
    *reinterpret_cast<uint2*>(dst) = p;
}

// ============================================================================
// fp16 GEMM:  C[m,n] = sum_k A[m,k]*W[n,k] + bias[n]
// BM=64, BN=128, BK=64, 128 thr (2m x 2n warps, warp tile 32x64).
// 4 CTAs/SM; single-sync pipeline (wait -> sync -> issue next -> compute).
// OutMode: 0 = fp32 out, 1 = fp16 out.
// ============================================================================
#define GROW 72
#define GA   (64 * GROW)            // A tile halves (64 rows)
#define GW   (128 * GROW)           // W tile halves (128 rows)
#define GSTG (GA + GW)              // halves per stage

template<int OutMode>
__device__ __forceinline__ void gemm_core(
    const __half* __restrict__ Ah, const __half* __restrict__ Wh,
    const float* __restrict__ bias,
    float* __restrict__ outF, __half* __restrict__ Oh)
{
    extern __shared__ __half sm[];
    const int tid  = threadIdx.x;
    const int lane = tid & 31;
    const int wid  = tid >> 5;          // 0..3
    const int wm   = wid & 1;           // 2 warps in m (32 rows each)
    const int wn   = wid >> 1;          // 2 warps in n (64 cols each)
    const int g    = lane >> 2;
    const int t4   = lane & 3;
    const int bm   = blockIdx.y * 64;
    const int bn   = blockIdx.x * 128;

    float acc[2][8][4];
#pragma unroll
    for (int s = 0; s < 2; ++s)
#pragma unroll
        for (int j = 0; j < 8; ++j)
#pragma unroll
            for (int e = 0; e < 4; ++e) acc[s][j][e] = 0.0f;

    // stage: A 64x64 + W 128x64 halves = 1536 cp16; 12 per thread
    auto load_stage = [&](int s, int kt) {
#pragma unroll
        for (int i = 0; i < 12; ++i) {
            const int idx = i * 128 + tid;        // [0, 1536)
            const bool isA = idx < 512;
            const int rem  = isA ? idx : (idx - 512);
            const int row  = rem >> 3;            // A: 0..63, W: 0..127
            const int col  = (rem & 7) * 8;
            const __half* base = isA ? Ah : Wh;
            const int rb = isA ? bm : bn;
            const uint32_t soff = isA ? (uint32_t)(row * GROW + col)
                                      : (uint32_t)(GA + row * GROW + col);
            cp16(smem_u32(sm + (uint32_t)s * GSTG + soff),
                 base + (size_t)(rb + row) * E_DIM + kt + col);
        }
    };

    load_stage(0, 0);
    CP_COMMIT();

    const int NT = E_DIM / 64;   // 16
    for (int t = 0; t < NT; ++t) {
        const int s = t & 1;
        CP_WAIT0();
        __syncthreads();
        if (t + 1 < NT) {
            load_stage(s ^ 1, (t + 1) * 64);
            CP_COMMIT();
        }

        const uint32_t bAh = smem_u32(sm + (uint32_t)s * GSTG);
        const uint32_t bWh = smem_u32(sm + (uint32_t)s * GSTG + GA);

#pragma unroll
        for (int kk = 0; kk < 4; ++kk) {
            uint32_t ah[2][4];
            const int ka = kk * 16 + (lane >> 4) * 8;
#pragma unroll
            for (int ss = 0; ss < 2; ++ss) {
                const int m = wm * 32 + ss * 16 + (lane & 15);
                const uint32_t off = (uint32_t)(m * GROW + ka) * 2;
                ldsm4(ah[ss][0], ah[ss][1], ah[ss][2], ah[ss][3], bAh + off);
            }
            const int kb  = kk * 16 + ((lane >> 3) & 1) * 8;
            const int nb0 = (lane & 7) + ((lane >> 4) << 3);
#pragma unroll
            for (int jp = 0; jp < 4; ++jp) {
                const int n = wn * 64 + jp * 16 + nb0;
                const uint32_t off = (uint32_t)(n * GROW + kb) * 2;
                uint32_t bh[4];
                ldsm4(bh[0], bh[1], bh[2], bh[3], bWh + off);
#pragma unroll
                for (int ss = 0; ss < 2; ++ss) {
                    mma_f16(acc[ss][2*jp],   ah[ss][0],ah[ss][1],ah[ss][2],ah[ss][3], bh[0],bh[1]);
                    mma_f16(acc[ss][2*jp+1], ah[ss][0],ah[ss][1],ah[ss][2],ah[ss][3], bh[2],bh[3]);
                }
            }
        }
    }

    // epilogue
#pragma unroll
    for (int j = 0; j < 8; ++j) {
        const int col = bn + wn * 64 + j * 8 + 2 * t4;
        const float b0 = bias[col], b1 = bias[col + 1];
#pragma unroll
        for (int ss = 0; ss < 2; ++ss) {
            const int r0 = bm + wm * 32 + ss * 16 + g;
            const float v0 = acc[ss][j][0] + b0, v1 = acc[ss][j][1] + b1;
            const float v2 = acc[ss][j][2] + b0, v3 = acc[ss][j][3] + b1;
            const size_t w0 = ((size_t)r0 * E_DIM + col) >> 1;
            const size_t w1 = ((size_t)(r0 + 8) * E_DIM + col) >> 1;
            if (OutMode == 1) {
                reinterpret_cast<uint32_t*>(Oh)[w0] = pack2h(v0, v1);
                reinterpret_cast<uint32_t*>(Oh)[w1] = pack2h(v2, v3);
            } else {
                float2 p0; p0.x = v0; p0.y = v1;
                float2 p1; p1.x = v2; p1.y = v3;
                *reinterpret_cast<float2*>(outF + (size_t)r0 * E_DIM + col) = p0;
                *reinterpret_cast<float2*>(outF + (size_t)(r0 + 8) * E_DIM + col) = p1;
            }
        }
    }
}

__global__ __launch_bounds__(128, 4) void qkv_kernel(
    const float* __restrict__ bq, const float* __restrict__ bk,
    const float* __restrict__ bv)
{
    const int z = blockIdx.z;
    const __half* Wh = g_wh + (size_t)z * WELEM;
    const float* bias = (z == 0) ? bq : (z == 1) ? bk : bv;
    __half* Oh = (z == 0) ? g_qh : (z == 1) ? g_kh : g_vh;
    gemm_core<1>(g_xh, Wh, bias, nullptr, Oh);
}

__global__ __launch_bounds__(128, 4) void outproj_kernel(
    const float* __restrict__ bo, float* __restrict__ out)
{
    gemm_core<0>(g_ah, g_wh + (size_t)3 * WELEM, bo, out, nullptr);
}

// ============================================================================
// Flash attention: 256 thr (8 warps), Q tile 128, K tiles of 64.
// Single-sync pipeline.  QK^T: 1 MMA.  PV: 1 MMA.  Output fp16.
// ============================================================================
#define APAD 72
#define AT   (64 * APAD)
#define ATTN_SMEM (2 * 2 * AT * 2)   // 36864 B

__global__ __launch_bounds__(256) void attn_kernel()
{
    extern __shared__ __half sm[];
    const int tid  = threadIdx.x;
    const int lane = tid & 31;
    const int wid  = tid >> 5;          // 0..7
    const int g    = lane >> 2;
    const int t4   = lane & 3;

    const int bh = blockIdx.y;
    const int b  = bh >> 4;
    const int h  = bh & 15;
    const int q0 = blockIdx.x * 128 + wid * 16;
    const size_t qrow0 = (size_t)(b * S_LEN + q0);

    const float cs = 0.18033688011112042f;   // (1/8) * log2(e)

    uint32_t qfh[4][4];
#pragma unroll
    for (int kk = 0; kk < 4; ++kk) {
        const size_t i0 = (qrow0 + g) * E_DIM + h * HD + kk * 16 + 2 * t4;
        const size_t i1 = (qrow0 + g + 8) * E_DIM + h * HD + kk * 16 + 2 * t4;
        qfh[kk][0] = *reinterpret_cast<const uint32_t*>(g_qh + i0);
        qfh[kk][1] = *reinterpret_cast<const uint32_t*>(g_qh + i1);
        qfh[kk][2] = *reinterpret_cast<const uint32_t*>(g_qh + i0 + 8);
        qfh[kk][3] = *reinterpret_cast<const uint32_t*>(g_qh + i1 + 8);
    }

    float oacc[8][4];
#pragma unroll
    for (int jd = 0; jd < 8; ++jd)
#pragma unroll
        for (int e = 0; e < 4; ++e) oacc[jd][e] = 0.0f;
    float m0 = -INFINITY, m1 = -INFINITY, l0 = 0.0f, l1 = 0.0f;

    auto load_stage = [&](int s, int kt) {
#pragma unroll
        for (int i = 0; i < 4; ++i) {
            const int idx = i * 256 + tid;       // [0, 1024)
            const int a   = idx >> 9;            // 0:Kh 1:Vh
            const int rem = idx & 511;
            const int row = rem >> 3;            // 0..63
            const int col = (rem & 7) * 8;
            const __half* base = (a == 0) ? g_kh : g_vh;
            cp16(smem_u32(sm + (s * 2 + a) * AT + row * APAD + col),
                 base + (size_t)(b * S_LEN + kt * 64 + row) * E_DIM + h * HD + col);
        }
    };

    load_stage(0, 0);
    CP_COMMIT();

    const int NT = S_LEN / 64;
    for (int t = 0; t < NT; ++t) {
        const int s = t & 1;
        CP_WAIT0();
        __syncthreads();
        if (t + 1 < NT) {
            load_stage(s ^ 1, t + 1);
            CP_COMMIT();
        }

        const uint32_t bKh = smem_u32(sm + (s * 2 + 0) * AT);
        const uint32_t bVh = smem_u32(sm + (s * 2 + 1) * AT);

        // ---- QK^T ----
        float sacc[8][4];
#pragma unroll
        for (int j = 0; j < 8; ++j)
#pragma unroll
            for (int e = 0; e < 4; ++e) sacc[j][e] = 0.0f;

        const int nb0 = (lane & 7) + ((lane >> 4) << 3);
        const int kb0 = ((lane >> 3) & 1) * 8;
#pragma unroll
        for (int jp = 0; jp < 4; ++jp) {
            const int n = jp * 16 + nb0;
#pragma unroll
            for (int kk = 0; kk < 4; ++kk) {
                const uint32_t off = (uint32_t)(n * APAD + kk * 16 + kb0) * 2;
                uint32_t kh[4];
                ldsm4(kh[0], kh[1], kh[2], kh[3], bKh + off);
                mma_f16(sacc[2*jp],   qfh[kk][0],qfh[kk][1],qfh[kk][2],qfh[kk][3], kh[0],kh[1]);
                mma_f16(sacc[2*jp+1], qfh[kk][0],qfh[kk][1],qfh[kk][2],qfh[kk][3], kh[2],kh[3]);
            }
        }

        // ---- online softmax ----
        float nm0 = m0, nm1 = m1;
#pragma unroll
        for (int j = 0; j < 8; ++j) {
            nm0 = fmaxf(nm0, fmaxf(sacc[j][0], sacc[j][1]));
            nm1 = fmaxf(nm1, fmaxf(sacc[j][2], sacc[j][3]));
        }
        nm0 = fmaxf(nm0, __shfl_xor_sync(0xffffffffu, nm0, 1));
        nm0 = fmaxf(nm0, __shfl_xor_sync(0xffffffffu, nm0, 2));
        nm1 = fmaxf(nm1, __shfl_xor_sync(0xffffffffu, nm1, 1));
        nm1 = fmaxf(nm1, __shfl_xor_sync(0xffffffffu, nm1, 2));

        const float c0 = ex2f((m0 - nm0) * cs);
        const float c1 = ex2f((m1 - nm1) * cs);
        m0 = nm0; m1 = nm1;
        l0 *= c0;  l1 *= c1;

#pragma unroll
        for (int j = 0; j < 8; ++j) {
            const float p0 = ex2f((sacc[j][0] - m0) * cs);
            const float p1 = ex2f((sacc[j][1] - m0) * cs);
            const float p2 = ex2f((sacc[j][2] - m1) * cs);
            const float p3 = ex2f((sacc[j][3] - m1) * cs);
            l0 += p0 + p1;
            l1 += p2 + p3;
            sacc[j][0] = p0; sacc[j][1] = p1; sacc[j][2] = p2; sacc[j][3] = p3;
        }
#pragma unroll
        for (int jd = 0; jd < 8; ++jd) {
            oacc[jd][0] *= c0; oacc[jd][1] *= c0;
            oacc[jd][2] *= c1; oacc[jd][3] *= c1;
        }

        // ---- PV ----
        const int krb = ((lane >> 3) & 1) * 8 + (lane & 7);
        const int dcb = (lane >> 4) * 8;
#pragma unroll
        for (int kk = 0; kk < 4; ++kk) {
            uint32_t pah[4];
            pah[0] = pack2h(sacc[2*kk][0],   sacc[2*kk][1]);
            pah[1] = pack2h(sacc[2*kk][2],   sacc[2*kk][3]);
            pah[2] = pack2h(sacc[2*kk+1][0], sacc[2*kk+1][1]);
            pah[3] = pack2h(sacc[2*kk+1][2], sacc[2*kk+1][3]);
            const int kr = kk * 16 + krb;
#pragma unroll
            for (int jdp = 0; jdp < 4; ++jdp) {
                const int dc = jdp * 16 + dcb;
                const uint32_t off = (uint32_t)(kr * APAD + dc) * 2;
                uint32_t vh[4];
                ldsm4t(vh[0], vh[1], vh[2], vh[3], bVh + off);
                mma_f16(oacc[2*jdp],   pah[0],pah[1],pah[2],pah[3], vh[0],vh[1]);
                mma_f16(oacc[2*jdp+1], pah[0],pah[1],pah[2],pah[3], vh[2],vh[3]);
            }
        }
    }

    // ---- finalize: fp16 output ----
    l0 += __shfl_xor_sync(0xffffffffu, l0, 1);
    l0 += __shfl_xor_sync(0xffffffffu, l0, 2);
    l1 += __shfl_xor_sync(0xffffffffu, l1, 1);
    l1 += __shfl_xor_sync(0xffffffffu, l1, 2);
    const float inv0 = 1.0f / l0;
    const float inv1 = 1.0f / l1;

#pragma unroll
    for (int jd = 0; jd < 8; ++jd) {
        const int col = h * HD + jd * 8 + 2 * t4;
        const size_t w0 = ((qrow0 + g) * E_DIM + col) >> 1;
        const size_t w1 = ((qrow0 + g + 8) * E_DIM + col) >> 1;
        reinterpret_cast<uint32_t*>(g_ah)[w0] =
            pack2h(oacc[jd][0] * inv0, oacc[jd][1] * inv0);
        reinterpret_cast<uint32_t*>(g_ah)[w1] =
            pack2h(oacc[jd][2] * inv1, oacc[jd][3] * inv1);
    }
}

// ============================================================================
// Launch
// ============================================================================
#define GEMM_SMEM (2 * GSTG * 2)   // 55296 bytes

extern "C" void kernel_launch(void* const* d_in, const int* in_sizes, int n_in,
                              void* d_out, int out_size)
{
    const float* x  = (const float*)d_in[0];
    const float* bq = (const float*)d_in[2];
    const float* bk = (const float*)d_in[4];
    const float* bv = (const float*)d_in[6];
    const float* bo = (const float*)d_in[8];
    float* out = (float*)d_out;

    cudaFuncSetAttribute(qkv_kernel,
        cudaFuncAttributeMaxDynamicSharedMemorySize, GEMM_SMEM);
    cudaFuncSetAttribute(outproj_kernel,
        cudaFuncAttributeMaxDynamicSharedMemorySize, GEMM_SMEM);
    cudaFuncSetAttribute(attn_kernel,
        cudaFuncAttributeMaxDynamicSharedMemorySize, ATTN_SMEM);

    // 0) convert x and weights to fp16
    {
        const int total = (NELEM + 4 * WELEM) / 4;
        split_kernel<<<total / 256, 256>>>(x,
            (const float*)d_in[1], (const float*)d_in[3],
            (const float*)d_in[5], (const float*)d_in[7]);
    }
    // 1) fused QKV projections
    {
        dim3 grid(E_DIM / 128, MAX_M / 64, 3);    // (8, 64, 3)
        qkv_kernel<<<grid, 128, GEMM_SMEM>>>(bq, bk, bv);
    }
    // 2) flash attention
    {
        dim3 grid(S_LEN / 128, 2 * NH);
        attn_kernel<<<grid, 256, ATTN_SMEM>>>();
    }
    // 3) output projection
    {
        dim3 grid(E_DIM / 128, MAX_M / 64);       // (8, 64)
        outproj_kernel<<<grid, 128, GEMM_SMEM>>>(bo, out);
    }
}

// round 15
// speedup vs baseline: 1.0191x; 1.0191x over previous
#include <cuda_runtime.h>
#include <cuda_fp16.h>
#include <math.h>
#include <stdint.h>

// ============================================================================
// B=2, S=2048, E=1024, H=16, D=64.  M = 4096.
// All matmuls 1-term fp16 on mma.sync (HMMA; tcgen05 not compilable here).
// GEMMs: round-12 config (BM=128/BN=128/BK=64, 256 thr, single-sync pipeline).
// Attention: QK^T on f16-ACCUMULATOR HMMA (potentially 2x rate); PV f32 acc.
// (Byte-identical resubmission of round-14 source: container failure was a
//  known infra flake pattern — this kernel has no hang-capable constructs.)
// ============================================================================

#define E_DIM 1024
#define NH    16
#define HD    64
#define S_LEN 2048
#define MAX_M 4096
#define NELEM 4194304
#define WELEM 1048576

__device__ __half g_xh[NELEM];
__device__ __half g_wh[4 * WELEM];
__device__ __half g_qh[NELEM];
__device__ __half g_kh[NELEM];
__device__ __half g_vh[NELEM];
__device__ __half g_ah[NELEM];     // attention output (fp16), outproj A-side

// ---- helpers ----
__device__ __forceinline__ void mma_f16(float c[4],
    uint32_t a0, uint32_t a1, uint32_t a2, uint32_t a3,
    uint32_t b0, uint32_t b1)
{
    asm volatile(
        "mma.sync.aligned.m16n8k16.row.col.f32.f16.f16.f32 "
        "{%0,%1,%2,%3}, {%4,%5,%6,%7}, {%8,%9}, {%0,%1,%2,%3};"
        : "+f"(c[0]), "+f"(c[1]), "+f"(c[2]), "+f"(c[3])
        : "r"(a0), "r"(a1), "r"(a2), "r"(a3), "r"(b0), "r"(b1));
}

// f16-accumulator variant: D/C are 2 packed f16x2 registers
__device__ __forceinline__ void mma_f16h(uint32_t& c0, uint32_t& c1,
    uint32_t a0, uint32_t a1, uint32_t a2, uint32_t a3,
    uint32_t b0, uint32_t b1)
{
    asm volatile(
        "mma.sync.aligned.m16n8k16.row.col.f16.f16.f16.f16 "
        "{%0,%1}, {%2,%3,%4,%5}, {%6,%7}, {%0,%1};"
        : "+r"(c0), "+r"(c1)
        : "r"(a0), "r"(a1), "r"(a2), "r"(a3), "r"(b0), "r"(b1));
}

__device__ __forceinline__ float ex2f(float x) {
    float y;
    asm("ex2.approx.ftz.f32 %0, %1;" : "=f"(y) : "f"(x));
    return y;
}

__device__ __forceinline__ uint32_t pack2h(float x, float y) {
    __half2 t = __halves2half2(__float2half_rn(x), __float2half_rn(y));
    return *reinterpret_cast<uint32_t*>(&t);
}

__device__ __forceinline__ uint32_t smem_u32(const void* p) {
    return (uint32_t)__cvta_generic_to_shared(p);
}

__device__ __forceinline__ void ldsm4(uint32_t& r0, uint32_t& r1,
                                      uint32_t& r2, uint32_t& r3, uint32_t a) {
    asm volatile("ldmatrix.sync.aligned.m8n8.x4.shared.b16 {%0,%1,%2,%3}, [%4];"
        : "=r"(r0), "=r"(r1), "=r"(r2), "=r"(r3) : "r"(a));
}

__device__ __forceinline__ void ldsm4t(uint32_t& r0, uint32_t& r1,
                                       uint32_t& r2, uint32_t& r3, uint32_t a) {
    asm volatile("ldmatrix.sync.aligned.m8n8.x4.trans.shared.b16 {%0,%1,%2,%3}, [%4];"
        : "=r"(r0), "=r"(r1), "=r"(r2), "=r"(r3) : "r"(a));
}

__device__ __forceinline__ void cp16(uint32_t dst, const void* src) {
    asm volatile("cp.async.cg.shared.global [%0], [%1], 16;"
        :: "r"(dst), "l"(src));
}
#define CP_COMMIT() asm volatile("cp.async.commit_group;")
#define CP_WAIT0()  asm volatile("cp.async.wait_group 0;")

// ============================================================================
// Convert: x and 4 weight matrices -> fp16 (float4-vectorized)
// ============================================================================
__global__ __launch_bounds__(256) void split_kernel(
    const float* __restrict__ x,
    const float* __restrict__ Wq, const float* __restrict__ Wk,
    const float* __restrict__ Wv, const float* __restrict__ Wo)
{
    const int i4 = (blockIdx.x * 256 + threadIdx.x) * 4;
    const float* src;
    __half* dst;
    if (i4 < NELEM) {
        src = x + i4;
        dst = g_xh + i4;
    } else {
        const int j4 = i4 - NELEM;
        const int w  = j4 >> 20;
        const int off = j4 & (WELEM - 1);
        const float* W = (w == 0) ? Wq : (w == 1) ? Wk : (w == 2) ? Wv : Wo;
        src = W + off;
        dst = g_wh + j4;
    }
    const float4 v = *reinterpret_cast<const float4*>(src);
    uint2 p;
    p.x = pack2h(v.x, v.y);
    p.y = pack2h(v.z, v.w);
    *reinterpret_cast<uint2*>(dst) = p;
}

// ============================================================================
// fp16 GEMM (round-12 config):  C[m,n] = sum_k A[m,k]*W[n,k] + bias[n]
// BM=128, BN=128, BK=64, 256 thr (4m x 2n warps, warp tile 32x64).
// Single-sync pipeline.  OutMode: 0 = fp32 out, 1 = fp16 out.
// ============================================================================
#define GROW 72
#define GT   (128 * GROW)      // halves per array per stage

template<int OutMode>
__device__ __forceinline__ void gemm_core(
    const __half* __restrict__ Ah, const __half* __restrict__ Wh,
    const float* __restrict__ bias,
    float* __restrict__ outF, __half* __restrict__ Oh)
{
    extern __shared__ __half sm[];
    const int tid  = threadIdx.x;
    const int lane = tid & 31;
    const int wid  = tid >> 5;
    const int wm   = wid & 3;
    const int wn   = wid >> 2;
    const int g    = lane >> 2;
    const int t4   = lane & 3;
    const int bm   = blockIdx.y * 128;
    const int bn   = blockIdx.x * 128;

    float acc[2][8][4];
#pragma unroll
    for (int s = 0; s < 2; ++s)
#pragma unroll
        for (int j = 0; j < 8; ++j)
#pragma unroll
            for (int e = 0; e < 4; ++e) acc[s][j][e] = 0.0f;

    auto load_stage = [&](int s, int kt) {
#pragma unroll
        for (int i = 0; i < 8; ++i) {
            const int idx = i * 256 + tid;        // [0, 2048)
            const int a   = idx >> 10;            // 0:A 1:W
            const int rem = idx & 1023;
            const int row = rem >> 3;             // 0..127
            const int col = (rem & 7) * 8;        // 0..56
            const __half* base = (a == 0) ? Ah : Wh;
            const int rb = (a == 0) ? bm : bn;
            cp16(smem_u32(sm + (s * 2 + a) * GT + row * GROW + col),
                 base + (size_t)(rb + row) * E_DIM + kt + col);
        }
    };

    load_stage(0, 0);
    CP_COMMIT();

    const int NT = E_DIM / 64;   // 16
    for (int t = 0; t < NT; ++t) {
        const int s = t & 1;
        CP_WAIT0();
        __syncthreads();
        if (t + 1 < NT) {
            load_stage(s ^ 1, (t + 1) * 64);
            CP_COMMIT();
        }

        const uint32_t bAh = smem_u32(sm + (s * 2 + 0) * GT);
        const uint32_t bWh = smem_u32(sm + (s * 2 + 1) * GT);

#pragma unroll
        for (int kk = 0; kk < 4; ++kk) {
            uint32_t ah[2][4];
            const int ka = kk * 16 + (lane >> 4) * 8;
#pragma unroll
            for (int ss = 0; ss < 2; ++ss) {
                const int m = wm * 32 + ss * 16 + (lane & 15);
                const uint32_t off = (uint32_t)(m * GROW + ka) * 2;
                ldsm4(ah[ss][0], ah[ss][1], ah[ss][2], ah[ss][3], bAh + off);
            }
            const int kb  = kk * 16 + ((lane >> 3) & 1) * 8;
            const int nb0 = (lane & 7) + ((lane >> 4) << 3);
#pragma unroll
            for (int jp = 0; jp < 4; ++jp) {
                const int n = wn * 64 + jp * 16 + nb0;
                const uint32_t off = (uint32_t)(n * GROW + kb) * 2;
                uint32_t bh[4];
                ldsm4(bh[0], bh[1], bh[2], bh[3], bWh + off);
#pragma unroll
                for (int ss = 0; ss < 2; ++ss) {
                    mma_f16(acc[ss][2*jp],   ah[ss][0],ah[ss][1],ah[ss][2],ah[ss][3], bh[0],bh[1]);
                    mma_f16(acc[ss][2*jp+1], ah[ss][0],ah[ss][1],ah[ss][2],ah[ss][3], bh[2],bh[3]);
                }
            }
        }
    }

    // epilogue
#pragma unroll
    for (int j = 0; j < 8; ++j) {
        const int col = bn + wn * 64 + j * 8 + 2 * t4;
        const float b0 = bias[col], b1 = bias[col + 1];
#pragma unroll
        for (int ss = 0; ss < 2; ++ss) {
            const int r0 = bm + wm * 32 + ss * 16 + g;
            const float v0 = acc[ss][j][0] + b0, v1 = acc[ss][j][1] + b1;
            const float v2 = acc[ss][j][2] + b0, v3 = acc[ss][j][3] + b1;
            const size_t w0 = ((size_t)r0 * E_DIM + col) >> 1;
            const size_t w1 = ((size_t)(r0 + 8) * E_DIM + col) >> 1;
            if (OutMode == 1) {
                reinterpret_cast<uint32_t*>(Oh)[w0] = pack2h(v0, v1);
                reinterpret_cast<uint32_t*>(Oh)[w1] = pack2h(v2, v3);
            } else {
                float2 p0; p0.x = v0; p0.y = v1;
                float2 p1; p1.x = v2; p1.y = v3;
                *reinterpret_cast<float2*>(outF + (size_t)r0 * E_DIM + col) = p0;
                *reinterpret_cast<float2*>(outF + (size_t)(r0 + 8) * E_DIM + col) = p1;
            }
        }
    }
}

__global__ __launch_bounds__(256, 2) void qkv_kernel(
    const float* __restrict__ bq, const float* __restrict__ bk,
    const float* __restrict__ bv)
{
    const int z = blockIdx.z;
    const __half* Wh = g_wh + (size_t)z * WELEM;
    const float* bias = (z == 0) ? bq : (z == 1) ? bk : bv;
    __half* Oh = (z == 0) ? g_qh : (z == 1) ? g_kh : g_vh;
    gemm_core<1>(g_xh, Wh, bias, nullptr, Oh);
}

__global__ __launch_bounds__(256, 2) void outproj_kernel(
    const float* __restrict__ bo, float* __restrict__ out)
{
    gemm_core<0>(g_ah, g_wh + (size_t)3 * WELEM, bo, out, nullptr);
}

// ============================================================================
// Flash attention: 256 thr (8 warps), Q tile 128, K tiles of 64.
// QK^T: f16-accumulator HMMA.  PV: f32 acc.  Single-sync pipeline.
// ============================================================================
#define APAD 72
#define AT   (64 * APAD)
#define ATTN_SMEM (2 * 2 * AT * 2)   // 36864 B

__global__ __launch_bounds__(256) void attn_kernel()
{
    extern __shared__ __half sm[];
    const int tid  = threadIdx.x;
    const int lane = tid & 31;
    const int wid  = tid >> 5;          // 0..7
    const int g    = lane >> 2;
    const int t4   = lane & 3;

    const int bh = blockIdx.y;
    const int b  = bh >> 4;
    const int h  = bh & 15;
    const int q0 = blockIdx.x * 128 + wid * 16;
    const size_t qrow0 = (size_t)(b * S_LEN + q0);

    const float cs = 0.18033688011112042f;   // (1/8) * log2(e)

    uint32_t qfh[4][4];
#pragma unroll
    for (int kk = 0; kk < 4; ++kk) {
        const size_t i0 = (qrow0 + g) * E_DIM + h * HD + kk * 16 + 2 * t4;
        const size_t i1 = (qrow0 + g + 8) * E_DIM + h * HD + kk * 16 + 2 * t4;
        qfh[kk][0] = *reinterpret_cast<const uint32_t*>(g_qh + i0);
        qfh[kk][1] = *reinterpret_cast<const uint32_t*>(g_qh + i1);
        qfh[kk][2] = *reinterpret_cast<const uint32_t*>(g_qh + i0 + 8);
        qfh[kk][3] = *reinterpret_cast<const uint32_t*>(g_qh + i1 + 8);
    }

    float oacc[8][4];
#pragma unroll
    for (int jd = 0; jd < 8; ++jd)
#pragma unroll
        for (int e = 0; e < 4; ++e) oacc[jd][e] = 0.0f;
    float m0 = -INFINITY, m1 = -INFINITY, l0 = 0.0f, l1 = 0.0f;

    auto load_stage = [&](int s, int kt) {
#pragma unroll
        for (int i = 0; i < 4; ++i) {
            const int idx = i * 256 + tid;       // [0, 1024)
            const int a   = idx >> 9;            // 0:Kh 1:Vh
            const int rem = idx & 511;
            const int row = rem >> 3;            // 0..63
            const int col = (rem & 7) * 8;
            const __half* base = (a == 0) ? g_kh : g_vh;
            cp16(smem_u32(sm + (s * 2 + a) * AT + row * APAD + col),
                 base + (size_t)(b * S_LEN + kt * 64 + row) * E_DIM + h * HD + col);
        }
    };

    load_stage(0, 0);
    CP_COMMIT();

    const int NT = S_LEN / 64;
    for (int t = 0; t < NT; ++t) {
        const int s = t & 1;
        CP_WAIT0();
        __syncthreads();
        if (t + 1 < NT) {
            load_stage(s ^ 1, t + 1);
            CP_COMMIT();
        }

        const uint32_t bKh = smem_u32(sm + (s * 2 + 0) * AT);
        const uint32_t bVh = smem_u32(sm + (s * 2 + 1) * AT);

        // ---- QK^T with f16 accumulator ----
        uint32_t hacc[8][2];
#pragma unroll
        for (int j = 0; j < 8; ++j) { hacc[j][0] = 0u; hacc[j][1] = 0u; }

        const int nb0 = (lane & 7) + ((lane >> 4) << 3);
        const int kb0 = ((lane >> 3) & 1) * 8;
#pragma unroll
        for (int jp = 0; jp < 4; ++jp) {
            const int n = jp * 16 + nb0;
#pragma unroll
            for (int kk = 0; kk < 4; ++kk) {
                const uint32_t off = (uint32_t)(n * APAD + kk * 16 + kb0) * 2;
                uint32_t kh[4];
                ldsm4(kh[0], kh[1], kh[2], kh[3], bKh + off);
                mma_f16h(hacc[2*jp][0],   hacc[2*jp][1],
                         qfh[kk][0],qfh[kk][1],qfh[kk][2],qfh[kk][3], kh[0],kh[1]);
                mma_f16h(hacc[2*jp+1][0], hacc[2*jp+1][1],
                         qfh[kk][0],qfh[kk][1],qfh[kk][2],qfh[kk][3], kh[2],kh[3]);
            }
        }

        // unpack to f32 for softmax
        float sacc[8][4];
#pragma unroll
        for (int j = 0; j < 8; ++j) {
            const __half2 h0 = *reinterpret_cast<const __half2*>(&hacc[j][0]);
            const __half2 h1 = *reinterpret_cast<const __half2*>(&hacc[j][1]);
            sacc[j][0] = __low2float(h0);  sacc[j][1] = __high2float(h0);
            sacc[j][2] = __low2float(h1);  sacc[j][3] = __high2float(h1);
        }

        // ---- online softmax ----
        float nm0 = m0, nm1 = m1;
#pragma unroll
        for (int j = 0; j < 8; ++j) {
            nm0 = fmaxf(nm0, fmaxf(sacc[j][0], sacc[j][1]));
            nm1 = fmaxf(nm1, fmaxf(sacc[j][2], sacc[j][3]));
        }
        nm0 = fmaxf(nm0, __shfl_xor_sync(0xffffffffu, nm0, 1));
        nm0 = fmaxf(nm0, __shfl_xor_sync(0xffffffffu, nm0, 2));
        nm1 = fmaxf(nm1, __shfl_xor_sync(0xffffffffu, nm1, 1));
        nm1 = fmaxf(nm1, __shfl_xor_sync(0xffffffffu, nm1, 2));

        const float c0 = ex2f((m0 - nm0) * cs);
        const float c1 = ex2f((m1 - nm1) * cs);
        m0 = nm0; m1 = nm1;
        l0 *= c0;  l1 *= c1;

#pragma unroll
        for (int j = 0; j < 8; ++j) {
            const float p0 = ex2f((sacc[j][0] - m0) * cs);
            const float p1 = ex2f((sacc[j][1] - m0) * cs);
            const float p2 = ex2f((sacc[j][2] - m1) * cs);
            const float p3 = ex2f((sacc[j][3] - m1) * cs);
            l0 += p0 + p1;
            l1 += p2 + p3;
            sacc[j][0] = p0; sacc[j][1] = p1; sacc[j][2] = p2; sacc[j][3] = p3;
        }
#pragma unroll
        for (int jd = 0; jd < 8; ++jd) {
            oacc[jd][0] *= c0; oacc[jd][1] *= c0;
            oacc[jd][2] *= c1; oacc[jd][3] *= c1;
        }

        // ---- PV (f32 acc) ----
        const int krb = ((lane >> 3) & 1) * 8 + (lane & 7);
        const int dcb = (lane >> 4) * 8;
#pragma unroll
        for (int kk = 0; kk < 4; ++kk) {
            uint32_t pah[4];
            pah[0] = pack2h(sacc[2*kk][0],   sacc[2*kk][1]);
            pah[1] = pack2h(sacc[2*kk][2],   sacc[2*kk][3]);
            pah[2] = pack2h(sacc[2*kk+1][0], sacc[2*kk+1][1]);
            pah[3] = pack2h(sacc[2*kk+1][2], sacc[2*kk+1][3]);
            const int kr = kk * 16 + krb;
#pragma unroll
            for (int jdp = 0; jdp < 4; ++jdp) {
                const int dc = jdp * 16 + dcb;
                const uint32_t off = (uint32_t)(kr * APAD + dc) * 2;
                uint32_t vh[4];
                ldsm4t(vh[0], vh[1], vh[2], vh[3], bVh + off);
                mma_f16(oacc[2*jdp],   pah[0],pah[1],pah[2],pah[3], vh[0],vh[1]);
                mma_f16(oacc[2*jdp+1], pah[0],pah[1],pah[2],pah[3], vh[2],vh[3]);
            }
        }
    }

    // ---- finalize: fp16 output ----
    l0 += __shfl_xor_sync(0xffffffffu, l0, 1);
    l0 += __shfl_xor_sync(0xffffffffu, l0, 2);
    l1 += __shfl_xor_sync(0xffffffffu, l1, 1);
    l1 += __shfl_xor_sync(0xffffffffu, l1, 2);
    const float inv0 = 1.0f / l0;
    const float inv1 = 1.0f / l1;

#pragma unroll
    for (int jd = 0; jd < 8; ++jd) {
        const int col = h * HD + jd * 8 + 2 * t4;
        const size_t w0 = ((qrow0 + g) * E_DIM + col) >> 1;
        const size_t w1 = ((qrow0 + g + 8) * E_DIM + col) >> 1;
        reinterpret_cast<uint32_t*>(g_ah)[w0] =
            pack2h(oacc[jd][0] * inv0, oacc[jd][1] * inv0);
        reinterpret_cast<uint32_t*>(g_ah)[w1] =
            pack2h(oacc[jd][2] * inv1, oacc[jd][3] * inv1);
    }
}

// ============================================================================
// Launch
// ============================================================================
#define GEMM_SMEM (2 * 2 * GT * 2)   // 73728 bytes

extern "C" void kernel_launch(void* const* d_in, const int* in_sizes, int n_in,
                              void* d_out, int out_size)
{
    const float* x  = (const float*)d_in[0];
    const float* bq = (const float*)d_in[2];
    const float* bk = (const float*)d_in[4];
    const float* bv = (const float*)d_in[6];
    const float* bo = (const float*)d_in[8];
    float* out = (float*)d_out;

    cudaFuncSetAttribute(qkv_kernel,
        cudaFuncAttributeMaxDynamicSharedMemorySize, GEMM_SMEM);
    cudaFuncSetAttribute(outproj_kernel,
        cudaFuncAttributeMaxDynamicSharedMemorySize, GEMM_SMEM);
    cudaFuncSetAttribute(attn_kernel,
        cudaFuncAttributeMaxDynamicSharedMemorySize, ATTN_SMEM);

    // 0) convert x and weights to fp16
    {
        const int total = (NELEM + 4 * WELEM) / 4;
        split_kernel<<<total / 256, 256>>>(x,
            (const float*)d_in[1], (const float*)d_in[3],
            (const float*)d_in[5], (const float*)d_in[7]);
    }
    // 1) fused QKV projections
    {
        dim3 grid(E_DIM / 128, MAX_M / 128, 3);
        qkv_kernel<<<grid, 256, GEMM_SMEM>>>(bq, bk, bv);
    }
    // 2) flash attention
    {
        dim3 grid(S_LEN / 128, 2 * NH);
        attn_kernel<<<grid, 256, ATTN_SMEM>>>();
    }
    // 3) output projection
    {
        dim3 grid(E_DIM / 128, MAX_M / 128);
        outproj_kernel<<<grid, 256, GEMM_SMEM>>>(bo, out);
    }
}

// round 17
// speedup vs baseline: 1.0227x; 1.0035x over previous
#include <cuda_runtime.h>
#include <cuda_fp16.h>
#include <math.h>
#include <stdint.h>

// ============================================================================
// B=2, S=2048, E=1024, H=16, D=64.  M = 4096.
// All matmuls 1-term fp16 on mma.sync (HMMA; tcgen05 not compilable here).
// GEMMs: 128 thr / 4 warps, warp tile 64x64 (CUTLASS-classic) —
// 8 ldsm per 32 HMMA and 128 independent accumulators per warp.
// Attention: QK^T f16-acc HMMA, PV f32 acc (round-15 passing version).
// (Byte-identical resubmission of round-16 source: container failure matches
//  the twice-confirmed infra-flake pattern; kernel has no hang-capable code.)
// ============================================================================

#define E_DIM 1024
#define NH    16
#define HD    64
#define S_LEN 2048
#define MAX_M 4096
#define NELEM 4194304
#define WELEM 1048576

__device__ __half g_xh[NELEM];
__device__ __half g_wh[4 * WELEM];
__device__ __half g_qh[NELEM];
__device__ __half g_kh[NELEM];
__device__ __half g_vh[NELEM];
__device__ __half g_ah[NELEM];     // attention output (fp16), outproj A-side

// ---- helpers ----
__device__ __forceinline__ void mma_f16(float c[4],
    uint32_t a0, uint32_t a1, uint32_t a2, uint32_t a3,
    uint32_t b0, uint32_t b1)
{
    asm volatile(
        "mma.sync.aligned.m16n8k16.row.col.f32.f16.f16.f32 "
        "{%0,%1,%2,%3}, {%4,%5,%6,%7}, {%8,%9}, {%0,%1,%2,%3};"
        : "+f"(c[0]), "+f"(c[1]), "+f"(c[2]), "+f"(c[3])
        : "r"(a0), "r"(a1), "r"(a2), "r"(a3), "r"(b0), "r"(b1));
}

// f16-accumulator variant: D/C are 2 packed f16x2 registers
__device__ __forceinline__ void mma_f16h(uint32_t& c0, uint32_t& c1,
    uint32_t a0, uint32_t a1, uint32_t a2, uint32_t a3,
    uint32_t b0, uint32_t b1)
{
    asm volatile(
        "mma.sync.aligned.m16n8k16.row.col.f16.f16.f16.f16 "
        "{%0,%1}, {%2,%3,%4,%5}, {%6,%7}, {%0,%1};"
        : "+r"(c0), "+r"(c1)
        : "r"(a0), "r"(a1), "r"(a2), "r"(a3), "r"(b0), "r"(b1));
}

__device__ __forceinline__ float ex2f(float x) {
    float y;
    asm("ex2.approx.ftz.f32 %0, %1;" : "=f"(y) : "f"(x));
    return y;
}

__device__ __forceinline__ uint32_t pack2h(float x, float y) {
    __half2 t = __halves2half2(__float2half_rn(x), __float2half_rn(y));
    return *reinterpret_cast<uint32_t*>(&t);
}

__device__ __forceinline__ uint32_t smem_u32(const void* p) {
    return (uint32_t)__cvta_generic_to_shared(p);
}

__device__ __forceinline__ void ldsm4(uint32_t& r0, uint32_t& r1,
                                      uint32_t& r2, uint32_t& r3, uint32_t a) {
    asm volatile("ldmatrix.sync.aligned.m8n8.x4.shared.b16 {%0,%1,%2,%3}, [%4];"
        : "=r"(r0), "=r"(r1), "=r"(r2), "=r"(r3) : "r"(a));
}

__device__ __forceinline__ void ldsm4t(uint32_t& r0, uint32_t& r1,
                                       uint32_t& r2, uint32_t& r3, uint32_t a) {
    asm volatile("ldmatrix.sync.aligned.m8n8.x4.trans.shared.b16 {%0,%1,%2,%3}, [%4];"
        : "=r"(r0), "=r"(r1), "=r"(r2), "=r"(r3) : "r"(a));
}

__device__ __forceinline__ void cp16(uint32_t dst, const void* src) {
    asm volatile("cp.async.cg.shared.global [%0], [%1], 16;"
        :: "r"(dst), "l"(src));
}
#define CP_COMMIT() asm volatile("cp.async.commit_group;")
#define CP_WAIT0()  asm volatile("cp.async.wait_group 0;")

// ============================================================================
// Convert: x and 4 weight matrices -> fp16 (float4-vectorized)
// ============================================================================
__global__ __launch_bounds__(256) void split_kernel(
    const float* __restrict__ x,
    const float* __restrict__ Wq, const float* __restrict__ Wk,
    const float* __restrict__ Wv, const float* __restrict__ Wo)
{
    const int i4 = (blockIdx.x * 256 + threadIdx.x) * 4;
    const float* src;
    __half* dst;
    if (i4 < NELEM) {
        src = x + i4;
        dst = g_xh + i4;
    } else {
        const int j4 = i4 - NELEM;
        const int w  = j4 >> 20;
        const int off = j4 & (WELEM - 1);
        const float* W = (w == 0) ? Wq : (w == 1) ? Wk : (w == 2) ? Wv : Wo;
        src = W + off;
        dst = g_wh + j4;
    }
    const float4 v = *reinterpret_cast<const float4*>(src);
    uint2 p;
    p.x = pack2h(v.x, v.y);
    p.y = pack2h(v.z, v.w);
    *reinterpret_cast<uint2*>(dst) = p;
}

// ============================================================================
// fp16 GEMM:  C[m,n] = sum_k A[m,k]*W[n,k] + bias[n]
// BM=128, BN=128, BK=64; 128 thr, 4 warps (2m x 2n), warp tile 64x64.
// Per k16 step: 4 A-ldsm + 4 B-ldsm -> 32 HMMA; acc = 128 regs/thread.
// Single-sync pipeline.  OutMode: 0 = fp32 out, 1 = fp16 out.
// ============================================================================
#define GROW 72
#define GT   (128 * GROW)      // halves per array per stage

template<int OutMode>
__device__ __forceinline__ void gemm_core(
    const __half* __restrict__ Ah, const __half* __restrict__ Wh,
    const float* __restrict__ bias,
    float* __restrict__ outF, __half* __restrict__ Oh)
{
    extern __shared__ __half sm[];
    const int tid  = threadIdx.x;
    const int lane = tid & 31;
    const int wid  = tid >> 5;          // 0..3
    const int wm   = wid & 1;           // 2 warps in m (64 rows each)
    const int wn   = wid >> 1;          // 2 warps in n (64 cols each)
    const int g    = lane >> 2;
    const int t4   = lane & 3;
    const int bm   = blockIdx.y * 128;
    const int bn   = blockIdx.x * 128;

    float acc[4][8][4];                 // [m16-block][n8-block][frag]
#pragma unroll
    for (int ss = 0; ss < 4; ++ss)
#pragma unroll
        for (int j = 0; j < 8; ++j)
#pragma unroll
            for (int e = 0; e < 4; ++e) acc[ss][j][e] = 0.0f;

    // stage: 2 arrays x 128 rows x 64 halves; 2048 cp16; 16 per thread
    auto load_stage = [&](int s, int kt) {
#pragma unroll
        for (int i = 0; i < 16; ++i) {
            const int idx = i * 128 + tid;        // [0, 2048)
            const int a   = idx >> 10;            // 0:A 1:W
            const int rem = idx & 1023;
            const int row = rem >> 3;             // 0..127
            const int col = (rem & 7) * 8;        // 0..56
            const __half* base = (a == 0) ? Ah : Wh;
            const int rb = (a == 0) ? bm : bn;
            cp16(smem_u32(sm + (s * 2 + a) * GT + row * GROW + col),
                 base + (size_t)(rb + row) * E_DIM + kt + col);
        }
    };

    load_stage(0, 0);
    CP_COMMIT();

    const int NT = E_DIM / 64;   // 16
    for (int t = 0; t < NT; ++t) {
        const int s = t & 1;
        CP_WAIT0();
        __syncthreads();
        if (t + 1 < NT) {
            load_stage(s ^ 1, (t + 1) * 64);
            CP_COMMIT();
        }

        const uint32_t bAh = smem_u32(sm + (s * 2 + 0) * GT);
        const uint32_t bWh = smem_u32(sm + (s * 2 + 1) * GT);

#pragma unroll
        for (int kk = 0; kk < 4; ++kk) {
            uint32_t ah[4][4];
            const int ka = kk * 16 + (lane >> 4) * 8;
#pragma unroll
            for (int ss = 0; ss < 4; ++ss) {
                const int m = wm * 64 + ss * 16 + (lane & 15);
                const uint32_t off = (uint32_t)(m * GROW + ka) * 2;
                ldsm4(ah[ss][0], ah[ss][1], ah[ss][2], ah[ss][3], bAh + off);
            }
            const int kb  = kk * 16 + ((lane >> 3) & 1) * 8;
            const int nb0 = (lane & 7) + ((lane >> 4) << 3);
#pragma unroll
            for (int jp = 0; jp < 4; ++jp) {
                const int n = wn * 64 + jp * 16 + nb0;
                const uint32_t off = (uint32_t)(n * GROW + kb) * 2;
                uint32_t bh[4];
                ldsm4(bh[0], bh[1], bh[2], bh[3], bWh + off);
#pragma unroll
                for (int ss = 0; ss < 4; ++ss) {
                    mma_f16(acc[ss][2*jp],   ah[ss][0],ah[ss][1],ah[ss][2],ah[ss][3], bh[0],bh[1]);
                    mma_f16(acc[ss][2*jp+1], ah[ss][0],ah[ss][1],ah[ss][2],ah[ss][3], bh[2],bh[3]);
                }
            }
        }
    }

    // epilogue
#pragma unroll
    for (int j = 0; j < 8; ++j) {
        const int col = bn + wn * 64 + j * 8 + 2 * t4;
        const float b0 = bias[col], b1 = bias[col + 1];
#pragma unroll
        for (int ss = 0; ss < 4; ++ss) {
            const int r0 = bm + wm * 64 + ss * 16 + g;
            const float v0 = acc[ss][j][0] + b0, v1 = acc[ss][j][1] + b1;
            const float v2 = acc[ss][j][2] + b0, v3 = acc[ss][j][3] + b1;
            const size_t w0 = ((size_t)r0 * E_DIM + col) >> 1;
            const size_t w1 = ((size_t)(r0 + 8) * E_DIM + col) >> 1;
            if (OutMode == 1) {
                reinterpret_cast<uint32_t*>(Oh)[w0] = pack2h(v0, v1);
                reinterpret_cast<uint32_t*>(Oh)[w1] = pack2h(v2, v3);
            } else {
                float2 p0; p0.x = v0; p0.y = v1;
                float2 p1; p1.x = v2; p1.y = v3;
                *reinterpret_cast<float2*>(outF + (size_t)r0 * E_DIM + col) = p0;
                *reinterpret_cast<float2*>(outF + (size_t)(r0 + 8) * E_DIM + col) = p1;
            }
        }
    }
}

__global__ __launch_bounds__(128, 2) void qkv_kernel(
    const float* __restrict__ bq, const float* __restrict__ bk,
    const float* __restrict__ bv)
{
    const int z = blockIdx.z;
    const __half* Wh = g_wh + (size_t)z * WELEM;
    const float* bias = (z == 0) ? bq : (z == 1) ? bk : bv;
    __half* Oh = (z == 0) ? g_qh : (z == 1) ? g_kh : g_vh;
    gemm_core<1>(g_xh, Wh, bias, nullptr, Oh);
}

__global__ __launch_bounds__(128, 2) void outproj_kernel(
    const float* __restrict__ bo, float* __restrict__ out)
{
    gemm_core<0>(g_ah, g_wh + (size_t)3 * WELEM, bo, out, nullptr);
}

// ============================================================================
// Flash attention (round-15 passing version, unchanged):
// 256 thr (8 warps), Q tile 128, K tiles of 64, single-sync pipeline.
// QK^T: f16-accumulator HMMA.  PV: f32 acc.
// ============================================================================
#define APAD 72
#define AT   (64 * APAD)
#define ATTN_SMEM (2 * 2 * AT * 2)   // 36864 B

__global__ __launch_bounds__(256) void attn_kernel()
{
    extern __shared__ __half sm[];
    const int tid  = threadIdx.x;
    const int lane = tid & 31;
    const int wid  = tid >> 5;          // 0..7
    const int g    = lane >> 2;
    const int t4   = lane & 3;

    const int bh = blockIdx.y;
    const int b  = bh >> 4;
    const int h  = bh & 15;
    const int q0 = blockIdx.x * 128 + wid * 16;
    const size_t qrow0 = (size_t)(b * S_LEN + q0);

    const float cs = 0.18033688011112042f;   // (1/8) * log2(e)

    uint32_t qfh[4][4];
#pragma unroll
    for (int kk = 0; kk < 4; ++kk) {
        const size_t i0 = (qrow0 + g) * E_DIM + h * HD + kk * 16 + 2 * t4;
        const size_t i1 = (qrow0 + g + 8) * E_DIM + h * HD + kk * 16 + 2 * t4;
        qfh[kk][0] = *reinterpret_cast<const uint32_t*>(g_qh + i0);
        qfh[kk][1] = *reinterpret_cast<const uint32_t*>(g_qh + i1);
        qfh[kk][2] = *reinterpret_cast<const uint32_t*>(g_qh + i0 + 8);
        qfh[kk][3] = *reinterpret_cast<const uint32_t*>(g_qh + i1 + 8);
    }

    float oacc[8][4];
#pragma unroll
    for (int jd = 0; jd < 8; ++jd)
#pragma unroll
        for (int e = 0; e < 4; ++e) oacc[jd][e] = 0.0f;
    float m0 = -INFINITY, m1 = -INFINITY, l0 = 0.0f, l1 = 0.0f;

    auto load_stage = [&](int s, int kt) {
#pragma unroll
        for (int i = 0; i < 4; ++i) {
            const int idx = i * 256 + tid;       // [0, 1024)
            const int a   = idx >> 9;            // 0:Kh 1:Vh
            const int rem = idx & 511;
            const int row = rem >> 3;            // 0..63
            const int col = (rem & 7) * 8;
            const __half* base = (a == 0) ? g_kh : g_vh;
            cp16(smem_u32(sm + (s * 2 + a) * AT + row * APAD + col),
                 base + (size_t)(b * S_LEN + kt * 64 + row) * E_DIM + h * HD + col);
        }
    };

    load_stage(0, 0);
    CP_COMMIT();

    const int NT = S_LEN / 64;
    for (int t = 0; t < NT; ++t) {
        const int s = t & 1;
        CP_WAIT0();
        __syncthreads();
        if (t + 1 < NT) {
            load_stage(s ^ 1, t + 1);
            CP_COMMIT();
        }

        const uint32_t bKh = smem_u32(sm + (s * 2 + 0) * AT);
        const uint32_t bVh = smem_u32(sm + (s * 2 + 1) * AT);

        // ---- QK^T with f16 accumulator ----
        uint32_t hacc[8][2];
#pragma unroll
        for (int j = 0; j < 8; ++j) { hacc[j][0] = 0u; hacc[j][1] = 0u; }

        const int nb0 = (lane & 7) + ((lane >> 4) << 3);
        const int kb0 = ((lane >> 3) & 1) * 8;
#pragma unroll
        for (int jp = 0; jp < 4; ++jp) {
            const int n = jp * 16 + nb0;
#pragma unroll
            for (int kk = 0; kk < 4; ++kk) {
                const uint32_t off = (uint32_t)(n * APAD + kk * 16 + kb0) * 2;
                uint32_t kh[4];
                ldsm4(kh[0], kh[1], kh[2], kh[3], bKh + off);
                mma_f16h(hacc[2*jp][0],   hacc[2*jp][1],
                         qfh[kk][0],qfh[kk][1],qfh[kk][2],qfh[kk][3], kh[0],kh[1]);
                mma_f16h(hacc[2*jp+1][0], hacc[2*jp+1][1],
                         qfh[kk][0],qfh[kk][1],qfh[kk][2],qfh[kk][3], kh[2],kh[3]);
            }
        }

        // unpack to f32 for softmax
        float sacc[8][4];
#pragma unroll
        for (int j = 0; j < 8; ++j) {
            const __half2 h0 = *reinterpret_cast<const __half2*>(&hacc[j][0]);
            const __half2 h1 = *reinterpret_cast<const __half2*>(&hacc[j][1]);
            sacc[j][0] = __low2float(h0);  sacc[j][1] = __high2float(h0);
            sacc[j][2] = __low2float(h1);  sacc[j][3] = __high2float(h1);
        }

        // ---- online softmax ----
        float nm0 = m0, nm1 = m1;
#pragma unroll
        for (int j = 0; j < 8; ++j) {
            nm0 = fmaxf(nm0, fmaxf(sacc[j][0], sacc[j][1]));
            nm1 = fmaxf(nm1, fmaxf(sacc[j][2], sacc[j][3]));
        }
        nm0 = fmaxf(nm0, __shfl_xor_sync(0xffffffffu, nm0, 1));
        nm0 = fmaxf(nm0, __shfl_xor_sync(0xffffffffu, nm0, 2));
        nm1 = fmaxf(nm1, __shfl_xor_sync(0xffffffffu, nm1, 1));
        nm1 = fmaxf(nm1, __shfl_xor_sync(0xffffffffu, nm1, 2));

        const float c0 = ex2f((m0 - nm0) * cs);
        const float c1 = ex2f((m1 - nm1) * cs);
        m0 = nm0; m1 = nm1;
        l0 *= c0;  l1 *= c1;

#pragma unroll
        for (int j = 0; j < 8; ++j) {
            const float p0 = ex2f((sacc[j][0] - m0) * cs);
            const float p1 = ex2f((sacc[j][1] - m0) * cs);
            const float p2 = ex2f((sacc[j][2] - m1) * cs);
            const float p3 = ex2f((sacc[j][3] - m1) * cs);
            l0 += p0 + p1;
            l1 += p2 + p3;
            sacc[j][0] = p0; sacc[j][1] = p1; sacc[j][2] = p2; sacc[j][3] = p3;
        }
#pragma unroll
        for (int jd = 0; jd < 8; ++jd) {
            oacc[jd][0] *= c0; oacc[jd][1] *= c0;
            oacc[jd][2] *= c1; oacc[jd][3] *= c1;
        }

        // ---- PV (f32 acc) ----
        const int krb = ((lane >> 3) & 1) * 8 + (lane & 7);
        const int dcb = (lane >> 4) * 8;
#pragma unroll
        for (int kk = 0; kk < 4; ++kk) {
            uint32_t pah[4];
            pah[0] = pack2h(sacc[2*kk][0],   sacc[2*kk][1]);
            pah[1] = pack2h(sacc[2*kk][2],   sacc[2*kk][3]);
            pah[2] = pack2h(sacc[2*kk+1][0], sacc[2*kk+1][1]);
            pah[3] = pack2h(sacc[2*kk+1][2], sacc[2*kk+1][3]);
            const int kr = kk * 16 + krb;
#pragma unroll
            for (int jdp = 0; jdp < 4; ++jdp) {
                const int dc = jdp * 16 + dcb;
                const uint32_t off = (uint32_t)(kr * APAD + dc) * 2;
                uint32_t vh[4];
                ldsm4t(vh[0], vh[1], vh[2], vh[3], bVh + off);
                mma_f16(oacc[2*jdp],   pah[0],pah[1],pah[2],pah[3], vh[0],vh[1]);
                mma_f16(oacc[2*jdp+1], pah[0],pah[1],pah[2],pah[3], vh[2],vh[3]);
            }
        }
    }

    // ---- finalize: fp16 output ----
    l0 += __shfl_xor_sync(0xffffffffu, l0, 1);
    l0 += __shfl_xor_sync(0xffffffffu, l0, 2);
    l1 += __shfl_xor_sync(0xffffffffu, l1, 1);
    l1 += __shfl_xor_sync(0xffffffffu, l1, 2);
    const float inv0 = 1.0f / l0;
    const float inv1 = 1.0f / l1;

#pragma unroll
    for (int jd = 0; jd < 8; ++jd) {
        const int col = h * HD + jd * 8 + 2 * t4;
        const size_t w0 = ((qrow0 + g) * E_DIM + col) >> 1;
        const size_t w1 = ((qrow0 + g + 8) * E_DIM + col) >> 1;
        reinterpret_cast<uint32_t*>(g_ah)[w0] =
            pack2h(oacc[jd][0] * inv0, oacc[jd][1] * inv0);
        reinterpret_cast<uint32_t*>(g_ah)[w1] =
            pack2h(oacc[jd][2] * inv1, oacc[jd][3] * inv1);
    }
}

// ============================================================================
// Launch
// ============================================================================
#define GEMM_SMEM (2 * 2 * GT * 2)   // 73728 bytes

extern "C" void kernel_launch(void* const* d_in, const int* in_sizes, int n_in,
                              void* d_out, int out_size)
{
    const float* x  = (const float*)d_in[0];
    const float* bq = (const float*)d_in[2];
    const float* bk = (const float*)d_in[4];
    const float* bv = (const float*)d_in[6];
    const float* bo = (const float*)d_in[8];
    float* out = (float*)d_out;

    cudaFuncSetAttribute(qkv_kernel,
        cudaFuncAttributeMaxDynamicSharedMemorySize, GEMM_SMEM);
    cudaFuncSetAttribute(outproj_kernel,
        cudaFuncAttributeMaxDynamicSharedMemorySize, GEMM_SMEM);
    cudaFuncSetAttribute(attn_kernel,
        cudaFuncAttributeMaxDynamicSharedMemorySize, ATTN_SMEM);

    // 0) convert x and weights to fp16
    {
        const int total = (NELEM + 4 * WELEM) / 4;
        split_kernel<<<total / 256, 256>>>(x,
            (const float*)d_in[1], (const float*)d_in[3],
            (const float*)d_in[5], (const float*)d_in[7]);
    }
    // 1) fused QKV projections
    {
        dim3 grid(E_DIM / 128, MAX_M / 128, 3);
        qkv_kernel<<<grid, 128, GEMM_SMEM>>>(bq, bk, bv);
    }
    // 2) flash attention
    {
        dim3 grid(S_LEN / 128, 2 * NH);
        attn_kernel<<<grid, 256, ATTN_SMEM>>>();
    }
    // 3) output projection
    {
        dim3 grid(E_DIM / 128, MAX_M / 128);
        outproj_kernel<<<grid, 128, GEMM_SMEM>>>(bo, out);
    }
}